// round 11
// baseline (speedup 1.0000x reference)
#include <cuda_runtime.h>
#include <cstdint>
#include <cstddef>

#define T_STEPS 2048
#define BATCH   64
#define HID     256
#define NLAYER  2
#define MROWS   (T_STEPS * BATCH)       // 131072

// h_s: 16 slices of 16 k; slice stride 1028 floats (=4 mod 32 banks)
#define HS_SLICE 1028

// ---------------- scratch (static device memory; no allocation APIs) -------
__device__ float    g_pre[(size_t)NLAYER * MROWS * 1024];   // 1 GiB
__device__ float    g_h[NLAYER][2][HID * BATCH];            // TRANSPOSED [j][b]
__device__ unsigned g_cnt[NLAYER];

// ---------------- packed fp32x2 helpers ------------------------------------
__device__ __forceinline__ unsigned long long pack2(float x, float y) {
    unsigned long long r;
    asm("mov.b64 %0, {%1, %2};" : "=l"(r) : "f"(x), "f"(y));
    return r;
}
__device__ __forceinline__ void unpack2(unsigned long long v, float& x, float& y) {
    asm("mov.b64 {%0, %1}, %2;" : "=f"(x), "=f"(y) : "l"(v));
}
__device__ __forceinline__ void fma2(unsigned long long& d, unsigned long long a,
                                     unsigned long long b) {
    asm("fma.rn.f32x2 %0, %1, %2, %0;" : "+l"(d) : "l"(a), "l"(b));
}
__device__ __forceinline__ unsigned long long add2(unsigned long long a,
                                                   unsigned long long b) {
    unsigned long long r;
    asm("add.rn.f32x2 %0, %1, %2;" : "=l"(r) : "l"(a), "l"(b));
    return r;
}
__device__ __forceinline__ float sigmoidf_(float x) {
    return 1.0f / (1.0f + expf(-x));
}

// ---------------- kernel 1: pre[l,t,b,:] = x[t,b,:] @ Wx[l] + b[l] ---------
__global__ __launch_bounds__(256, 2) void k_pre(const float* __restrict__ x,
                                                const float* __restrict__ W,
                                                const float* __restrict__ bias) {
    __shared__ __align__(16) float As[32 * 132];
    __shared__ __align__(16) float Bs[32 * 128];

    if (blockIdx.x == 0 && threadIdx.x < NLAYER) g_cnt[threadIdx.x] = 0u;

    int bid  = blockIdx.x;
    int l    = bid >> 13;
    int rem  = bid & 8191;
    int mt   = rem >> 3;
    int nt   = rem & 7;
    int row0 = mt << 7;
    int col0 = nt << 7;
    int tid  = threadIdx.x;
    int tm   = tid >> 4;
    int tn   = tid & 15;

    const float* Wl = W + (size_t)l * 512 * 1024;

    unsigned long long acc[8][4];
#pragma unroll
    for (int i = 0; i < 8; i++)
#pragma unroll
        for (int j = 0; j < 4; j++) acc[i][j] = 0ULL;

    for (int kc = 0; kc < 256; kc += 32) {
#pragma unroll
        for (int i = 0; i < 4; i++) {
            int aidx = tid + i * 256;
            int m    = aidx >> 3;
            int k4   = (aidx & 7) << 2;
            float4 v = *(const float4*)&x[(size_t)(row0 + m) * 256 + kc + k4];
            As[(k4 + 0) * 132 + m] = v.x;
            As[(k4 + 1) * 132 + m] = v.y;
            As[(k4 + 2) * 132 + m] = v.z;
            As[(k4 + 3) * 132 + m] = v.w;
        }
#pragma unroll
        for (int i = 0; i < 4; i++) {
            int kk = (tid >> 5) + i * 8;
            int n4 = (tid & 31) << 2;
            *(float4*)&Bs[kk * 128 + n4] =
                *(const float4*)&Wl[(size_t)(kc + kk) * 1024 + col0 + n4];
        }
        __syncthreads();

#pragma unroll
        for (int k = 0; k < 32; k++) {
            float4 a0 = *(const float4*)&As[k * 132 + tm * 8];
            float4 a1 = *(const float4*)&As[k * 132 + tm * 8 + 4];
            ulonglong2 bb01 = *(const ulonglong2*)&Bs[k * 128 + tn * 8];
            ulonglong2 bb23 = *(const ulonglong2*)&Bs[k * 128 + tn * 8 + 4];
            float av[8] = {a0.x, a0.y, a0.z, a0.w, a1.x, a1.y, a1.z, a1.w};
#pragma unroll
            for (int i = 0; i < 8; i++) {
                unsigned long long a2 = pack2(av[i], av[i]);
                fma2(acc[i][0], a2, bb01.x);
                fma2(acc[i][1], a2, bb01.y);
                fma2(acc[i][2], a2, bb23.x);
                fma2(acc[i][3], a2, bb23.y);
            }
        }
        __syncthreads();
    }

    float bv[8];
#pragma unroll
    for (int j = 0; j < 8; j++) bv[j] = bias[l * 1024 + col0 + tn * 8 + j];
#pragma unroll
    for (int i = 0; i < 8; i++) {
        float o[8];
#pragma unroll
        for (int j = 0; j < 4; j++) unpack2(acc[i][j], o[2 * j], o[2 * j + 1]);
#pragma unroll
        for (int j = 0; j < 8; j++) o[j] += bv[j];
        size_t base = ((size_t)l * MROWS + row0 + tm * 8 + i) * 1024 + col0 + tn * 8;
        __stcs((float4*)&g_pre[base],     make_float4(o[0], o[1], o[2], o[3]));
        __stcs((float4*)&g_pre[base + 4], make_float4(o[4], o[5], o[6], o[7]));
    }
}

// ---------------- kernel 2: persistent recurrence ---------------------------
// 128 CTAs = 2 layers x 64 col-groups (4 hcols). 512 threads = 16 warps
// (4 per SMSP). warp = (b-octet bg = w>>1, hcol-pair hp = w&1).
// lane = ks(4b: 16-k slice) | ng(1b: hcol within pair).
// W in REGISTERS: 16k x (f,i)+(g,o) = 32 u64. Dot: 8b x 16k per thread.
// Reduce-scatter over ks (strides 16,8,4), final stride-2 exchange
// (duplicate across lane bit1). Pointwise: b = b_lo + (lane>>2).
__global__ __launch_bounds__(512, 1) void k_rec(const float* __restrict__ h0,
                                                const float* __restrict__ c0,
                                                const float* __restrict__ W,
                                                float* __restrict__ out) {
    extern __shared__ float smem[];
    float* h_s = smem;                      // 16*1028 = 16448 floats

    int l     = blockIdx.x >> 6;
    int cg    = blockIdx.x & 63;
    int c0col = cg << 2;
    int tid   = threadIdx.x;
    int w     = tid >> 5;
    int lane  = tid & 31;
    int ks    = lane >> 1;                  // 0..15 (16-k slice)
    int ng    = lane & 1;
    int bg    = w >> 1;                     // batch octet
    int b_lo  = bg << 3;
    int hcol  = c0col + ((w & 1) << 1) + ng;
    int b     = b_lo + (lane >> 2);         // pointwise batch row
    bool st_ok = (lane & 2) == 0;           // dedup predicate for stores

    // ---- W slice -> registers (persistent across all 2048 steps) ----
    unsigned long long wfi[16], wgo[16];
    {
        const float* Whl = W + (size_t)l * 512 * 1024 + (size_t)256 * 1024;
#pragma unroll
        for (int kk = 0; kk < 16; kk++) {
            const float* wr = Whl + (size_t)((ks << 4) + kk) * 1024 + hcol;
            wfi[kk] = pack2(wr[0], wr[256]);     // (f, i)
            wgo[kk] = pack2(wr[512], wr[768]);   // (g, o)
        }
    }

    // stage h0 transposed + swizzled: h_s[(j>>4)*1028 + (j&15)*64 + b]
    const float* h0l = h0 + l * BATCH * HID;
    for (int i = tid; i < 16384; i += 512) {
        int j = i >> 6, bb = i & 63;
        h_s[(j >> 4) * HS_SLICE + (j & 15) * 64 + bb] = h0l[bb * 256 + j];
    }
    float c = c0[l * BATCH * HID + b * 256 + hcol];
    float h_cur = 0.0f;
    __syncthreads();

    const float* hp = h_s + ks * HS_SLICE + b_lo;

    for (int t = 0; t < T_STEPS; t++) {
        // prefetch pre-activations (independent of everything below)
        size_t prow = ((size_t)l * MROWS + (size_t)t * BATCH + b) * 1024 + hcol;
        float pf = __ldcs(&g_pre[prow]);
        float pi = __ldcs(&g_pre[prow + 256]);
        float pg = __ldcs(&g_pre[prow + 512]);
        float po = __ldcs(&g_pre[prow + 768]);

        // 8b partial dot over this thread's 16-k slice; W from registers
        unsigned long long fi[8], go[8];
#pragma unroll
        for (int i = 0; i < 8; i++) { fi[i] = 0ULL; go[i] = 0ULL; }
#pragma unroll
        for (int kk = 0; kk < 16; kk++) {
            float4 hv0 = *(const float4*)&hp[kk << 6];
            float4 hv1 = *(const float4*)&hp[(kk << 6) + 4];
            float hh[8] = {hv0.x, hv0.y, hv0.z, hv0.w,
                           hv1.x, hv1.y, hv1.z, hv1.w};
#pragma unroll
            for (int bi = 0; bi < 8; bi++) {
                unsigned long long a2 = pack2(hh[bi], hh[bi]);
                fma2(fi[bi], a2, wfi[kk]);
                fma2(go[bi], a2, wgo[kk]);
            }
        }

        // reduce-scatter over ks bits 3..1 (lane bits 4..2): b bits 2..0
#pragma unroll
        for (int r = 0; r < 3; r++) {
            int stride = 16 >> r;     // 16, 8, 4
            int half   = 4 >> r;      // 4, 2, 1
            bool hi = (lane & stride) != 0;
#pragma unroll
            for (int i = 0; i < 4; i++) {
                if (i < half) {
                    unsigned long long sf = hi ? fi[i] : fi[i + half];
                    unsigned long long kf = hi ? fi[i + half] : fi[i];
                    fi[i] = add2(kf, __shfl_xor_sync(0xFFFFFFFFu, sf, stride));
                    unsigned long long sg = hi ? go[i] : go[i + half];
                    unsigned long long kg = hi ? go[i + half] : go[i];
                    go[i] = add2(kg, __shfl_xor_sync(0xFFFFFFFFu, sg, stride));
                }
            }
        }
        // final combine over ks bit0 (lane bit1); result duplicated
        fi[0] = add2(fi[0], __shfl_xor_sync(0xFFFFFFFFu, fi[0], 2));
        go[0] = add2(go[0], __shfl_xor_sync(0xFFFFFFFFu, go[0], 2));

        // pointwise for (b, hcol)
        float af, ai_, ag, ao;
        unpack2(fi[0], af, ai_);
        unpack2(go[0], ag, ao);
        float gf  = sigmoidf_(af + pf);
        float gi  = sigmoidf_(ai_ + pi);
        float gg  = tanhf(ag + pg);
        float go_ = sigmoidf_(ao + po);
        c     = gf * c + gi * gg;
        h_cur = go_ * tanhf(c);

        int wb = 1 - (t & 1);
        if (st_ok) {
            g_h[l][wb][hcol * 64 + b] = h_cur;                // transposed
            if (l == 1) out[(size_t)t * BATCH * HID + b * 256 + hcol] = h_cur;
        }

        if (t == T_STEPS - 1) break;

        __syncthreads();
        if (tid == 0) {
            asm volatile("red.release.gpu.global.add.u32 [%0], %1;"
                         :: "l"(&g_cnt[l]), "r"(1u) : "memory");
            unsigned target = 64u * (unsigned)(t + 1);
            unsigned v;
            do {
                asm volatile("ld.acquire.gpu.global.u32 %0, [%1];"
                             : "=r"(v) : "l"(&g_cnt[l]) : "memory");
            } while (v < target);
        }
        __syncthreads();

        // stage h_t (swizzled dst: float4 idx i -> i + (i>>8))
        const float4* src = (const float4*)g_h[l][wb];
        float4* dst = (float4*)h_s;
#pragma unroll
        for (int i = tid; i < 4096; i += 512) {
            dst[i + (i >> 8)] = __ldcg(&src[i]);
        }
        __syncthreads();
    }

    if (st_ok) {
        size_t OUTH = (size_t)T_STEPS * BATCH * HID;
        out[OUTH + (size_t)l * BATCH * HID + b * 256 + hcol]               = h_cur;
        out[OUTH + (size_t)NLAYER * BATCH * HID + (size_t)l * BATCH * HID
            + b * 256 + hcol]                                               = c;
    }
}

// ---------------- launch ----------------------------------------------------
extern "C" void kernel_launch(void* const* d_in, const int* in_sizes, int n_in,
                              void* d_out, int out_size) {
    const float* x    = (const float*)d_in[0];
    const float* h0   = (const float*)d_in[1];
    const float* c0   = (const float*)d_in[2];
    const float* W    = (const float*)d_in[3];
    const float* bias = (const float*)d_in[4];
    float* out = (float*)d_out;

    size_t dsmem = (size_t)(16 * HS_SLICE) * sizeof(float);   // 65,792 B
    cudaFuncSetAttribute(k_rec, cudaFuncAttributeMaxDynamicSharedMemorySize,
                         (int)dsmem);

    k_pre<<<NLAYER * (MROWS / 128) * (1024 / 128), 256>>>(x, W, bias);
    k_rec<<<NLAYER * 64, 512, dsmem>>>(h0, c0, W, out);
}

// round 13
// speedup vs baseline: 1.1848x; 1.1848x over previous
#include <cuda_runtime.h>
#include <cstdint>
#include <cstddef>

#define T_STEPS 2048
#define BATCH   64
#define HID     256
#define NLAYER  2
#define MROWS   (T_STEPS * BATCH)       // 131072

// h_s smem swizzle: 8 slices (32 k each); slice stride 524 floats,
// b-half offset 260, row stride 8 -> every LDS.128 resolves in 2 phases.
#define HS_SL   524
#define HS_HALF 260

// ---------------- scratch (static device memory; no allocation APIs) -------
__device__ float    g_pre[(size_t)NLAYER * MROWS * 1024];   // 1 GiB
__device__ float    g_h2[NLAYER][2][4][256 * 16];           // [l][buf][bR][j*16+b']
__device__ unsigned g_cnt2[NLAYER * 4][32];                 // padded counters

// ---------------- packed fp32x2 helpers ------------------------------------
__device__ __forceinline__ unsigned long long pack2(float x, float y) {
    unsigned long long r;
    asm("mov.b64 %0, {%1, %2};" : "=l"(r) : "f"(x), "f"(y));
    return r;
}
__device__ __forceinline__ void unpack2(unsigned long long v, float& x, float& y) {
    asm("mov.b64 {%0, %1}, %2;" : "=f"(x), "=f"(y) : "l"(v));
}
__device__ __forceinline__ void fma2(unsigned long long& d, unsigned long long a,
                                     unsigned long long b) {
    asm("fma.rn.f32x2 %0, %1, %2, %0;" : "+l"(d) : "l"(a), "l"(b));
}
__device__ __forceinline__ unsigned long long add2(unsigned long long a,
                                                   unsigned long long b) {
    unsigned long long r;
    asm("add.rn.f32x2 %0, %1, %2;" : "=l"(r) : "l"(a), "l"(b));
    return r;
}
__device__ __forceinline__ float sigmoidf_(float x) {
    return 1.0f / (1.0f + expf(-x));
}

// ---------------- kernel 1: pre[l,t,b,:] = x[t,b,:] @ Wx[l] + b[l] ---------
__global__ __launch_bounds__(256, 2) void k_pre(const float* __restrict__ x,
                                                const float* __restrict__ W,
                                                const float* __restrict__ bias) {
    __shared__ __align__(16) float As[32 * 132];
    __shared__ __align__(16) float Bs[32 * 128];

    if (blockIdx.x == 0 && threadIdx.x < NLAYER * 4)
        g_cnt2[threadIdx.x][0] = 0u;

    int bid  = blockIdx.x;
    int l    = bid >> 13;
    int rem  = bid & 8191;
    int mt   = rem >> 3;
    int nt   = rem & 7;
    int row0 = mt << 7;
    int col0 = nt << 7;
    int tid  = threadIdx.x;
    int tm   = tid >> 4;
    int tn   = tid & 15;

    const float* Wl = W + (size_t)l * 512 * 1024;

    unsigned long long acc[8][4];
#pragma unroll
    for (int i = 0; i < 8; i++)
#pragma unroll
        for (int j = 0; j < 4; j++) acc[i][j] = 0ULL;

    for (int kc = 0; kc < 256; kc += 32) {
#pragma unroll
        for (int i = 0; i < 4; i++) {
            int aidx = tid + i * 256;
            int m    = aidx >> 3;
            int k4   = (aidx & 7) << 2;
            float4 v = *(const float4*)&x[(size_t)(row0 + m) * 256 + kc + k4];
            As[(k4 + 0) * 132 + m] = v.x;
            As[(k4 + 1) * 132 + m] = v.y;
            As[(k4 + 2) * 132 + m] = v.z;
            As[(k4 + 3) * 132 + m] = v.w;
        }
#pragma unroll
        for (int i = 0; i < 4; i++) {
            int kk = (tid >> 5) + i * 8;
            int n4 = (tid & 31) << 2;
            *(float4*)&Bs[kk * 128 + n4] =
                *(const float4*)&Wl[(size_t)(kc + kk) * 1024 + col0 + n4];
        }
        __syncthreads();

#pragma unroll
        for (int k = 0; k < 32; k++) {
            float4 a0 = *(const float4*)&As[k * 132 + tm * 8];
            float4 a1 = *(const float4*)&As[k * 132 + tm * 8 + 4];
            ulonglong2 bb01 = *(const ulonglong2*)&Bs[k * 128 + tn * 8];
            ulonglong2 bb23 = *(const ulonglong2*)&Bs[k * 128 + tn * 8 + 4];
            float av[8] = {a0.x, a0.y, a0.z, a0.w, a1.x, a1.y, a1.z, a1.w};
#pragma unroll
            for (int i = 0; i < 8; i++) {
                unsigned long long a2 = pack2(av[i], av[i]);
                fma2(acc[i][0], a2, bb01.x);
                fma2(acc[i][1], a2, bb01.y);
                fma2(acc[i][2], a2, bb23.x);
                fma2(acc[i][3], a2, bb23.y);
            }
        }
        __syncthreads();
    }

    float bv[8];
#pragma unroll
    for (int j = 0; j < 8; j++) bv[j] = bias[l * 1024 + col0 + tn * 8 + j];
#pragma unroll
    for (int i = 0; i < 8; i++) {
        float o[8];
#pragma unroll
        for (int j = 0; j < 4; j++) unpack2(acc[i][j], o[2 * j], o[2 * j + 1]);
#pragma unroll
        for (int j = 0; j < 8; j++) o[j] += bv[j];
        size_t base = ((size_t)l * MROWS + row0 + tm * 8 + i) * 1024 + col0 + tn * 8;
        __stcs((float4*)&g_pre[base],     make_float4(o[0], o[1], o[2], o[3]));
        __stcs((float4*)&g_pre[base + 4], make_float4(o[4], o[5], o[6], o[7]));
    }
}

// ---------------- kernel 2: persistent recurrence ---------------------------
// 128 CTAs = 2 layers x 4 b-groups (16 b) x 16 hcol-groups (16 hcols).
// Barrier per (layer, b-group): 16 CTAs; staging = the CTA's own 16 KB
// b-slice of h. 256 threads = 8 warps. warp o = hcol pair-octet;
// lane = ks(3b: 32-k slice) | ng(2b). hc_in = o*2 + (ng&1); bhalf = ng>>1.
// Thread: 8 b x 4 gates x 32 k, W in REGISTERS. Reduce-scatter over ks.
__global__ __launch_bounds__(256, 1) void k_rec(const float* __restrict__ h0,
                                                const float* __restrict__ c0,
                                                const float* __restrict__ W,
                                                float* __restrict__ out) {
    __shared__ __align__(16) float h_s[8 * HS_SL];   // 16768 B

    int bid   = blockIdx.x;
    int l     = bid >> 6;
    int r     = bid & 63;
    int bR    = r >> 4;                 // b-group 0..3
    int hR    = r & 15;                 // hcol-group 0..15
    int b0    = bR << 4;
    int hcol0 = hR << 4;
    int tid   = threadIdx.x;
    int o     = tid >> 5;               // warp
    int lane  = tid & 31;
    int ks    = lane >> 2;              // 0..7 (32-k slice)
    int ng    = lane & 3;
    int hc_in = (o << 1) | (ng & 1);    // 0..15
    int hcol  = hcol0 + hc_in;          // global hidden index
    int bhalf = ng >> 1;
    int bq8   = bhalf << 3;
    int b_pw  = b0 + bq8 + ks;          // this lane's pointwise batch row
    unsigned* cnt = &g_cnt2[l * 4 + bR][0];

    // ---- W slice -> registers (persistent across all 2048 steps) ----
    unsigned long long wfi[32], wgo[32];
    {
        const float* Whl = W + (size_t)l * 512 * 1024 + (size_t)256 * 1024;
#pragma unroll
        for (int kk = 0; kk < 32; kk++) {
            const float* wr = Whl + (size_t)((ks << 5) + kk) * 1024 + hcol;
            wfi[kk] = pack2(wr[0], wr[256]);     // (f, i)
            wgo[kk] = pack2(wr[512], wr[768]);   // (g, o)
        }
    }

    // stage h0 slice [j][b'=0..15] -> swizzled smem
    const float* h0l = h0 + l * BATCH * HID;
    for (int i = tid; i < 4096; i += 256) {
        int j  = i >> 4;
        int bp = i & 15;
        int nh = bp >> 3;
        h_s[(j >> 5) * HS_SL + nh * HS_HALF + (j & 31) * 8 + (bp & 7)] =
            h0l[(b0 + bp) * 256 + j];
    }
    float c = c0[l * BATCH * HID + b_pw * 256 + hcol];
    float h_cur = 0.0f;
    __syncthreads();

    const float* hp = h_s + ks * HS_SL + bhalf * HS_HALF;

    for (int t = 0; t < T_STEPS; t++) {
        // prefetch pre-activations (independent of everything below)
        size_t prow = ((size_t)l * MROWS + (size_t)t * BATCH + b_pw) * 1024 + hcol;
        float pf = __ldcs(&g_pre[prow]);
        float pi = __ldcs(&g_pre[prow + 256]);
        float pg = __ldcs(&g_pre[prow + 512]);
        float po = __ldcs(&g_pre[prow + 768]);

        // 8b partial dot over this thread's 32-k slice; W from registers
        unsigned long long fi[8], go[8];
#pragma unroll
        for (int i = 0; i < 8; i++) { fi[i] = 0ULL; go[i] = 0ULL; }
#pragma unroll
        for (int kk = 0; kk < 32; kk++) {
            float4 hv0 = *(const float4*)&hp[kk << 3];
            float4 hv1 = *(const float4*)&hp[(kk << 3) + 4];
            float hh[8] = {hv0.x, hv0.y, hv0.z, hv0.w,
                           hv1.x, hv1.y, hv1.z, hv1.w};
#pragma unroll
            for (int bi = 0; bi < 8; bi++) {
                unsigned long long a2 = pack2(hh[bi], hh[bi]);
                fma2(fi[bi], a2, wfi[kk]);
                fma2(go[bi], a2, wgo[kk]);
            }
        }

        // reduce-scatter over ks (lane strides 16,8,4): lane ends with bi=ks
#pragma unroll
        for (int rd = 0; rd < 3; rd++) {
            int stride = 16 >> rd;     // 16, 8, 4
            int half   = 4 >> rd;      // 4, 2, 1
            bool hi = (lane & stride) != 0;
#pragma unroll
            for (int i = 0; i < 4; i++) {
                if (i < half) {
                    unsigned long long sf = hi ? fi[i] : fi[i + half];
                    unsigned long long kf = hi ? fi[i + half] : fi[i];
                    fi[i] = add2(kf, __shfl_xor_sync(0xFFFFFFFFu, sf, stride));
                    unsigned long long sg = hi ? go[i] : go[i + half];
                    unsigned long long kg = hi ? go[i + half] : go[i];
                    go[i] = add2(kg, __shfl_xor_sync(0xFFFFFFFFu, sg, stride));
                }
            }
        }

        // pointwise (every lane owns one (b_pw, hcol))
        float af, ai_, ag, ao;
        unpack2(fi[0], af, ai_);
        unpack2(go[0], ag, ao);
        float gf  = sigmoidf_(af + pf);
        float gi  = sigmoidf_(ai_ + pi);
        float gg  = tanhf(ag + pg);
        float go_ = sigmoidf_(ao + po);
        c     = gf * c + gi * gg;
        h_cur = go_ * tanhf(c);

        int wb = 1 - (t & 1);
        // GLOBAL hidden index row (bug fix vs round 12: hcol, not hc_in)
        g_h2[l][wb][bR][hcol * 16 + bq8 + ks] = h_cur;
        if (l == 1) out[(size_t)t * BATCH * HID + b_pw * 256 + hcol] = h_cur;

        if (t == T_STEPS - 1) break;

        __syncthreads();
        if (tid == 0) {
            asm volatile("red.release.gpu.global.add.u32 [%0], %1;"
                         :: "l"(cnt), "r"(1u) : "memory");
            unsigned target = 16u * (unsigned)(t + 1);
            unsigned v;
            do {
                asm volatile("ld.acquire.gpu.global.u32 %0, [%1];"
                             : "=r"(v) : "l"(cnt) : "memory");
            } while (v < target);
        }
        __syncthreads();

        // stage this b-group's h slice: contiguous 16 KB, 4 float4/thread
        const float4* src = (const float4*)g_h2[l][wb][bR];
#pragma unroll
        for (int q = 0; q < 4; q++) {
            int m   = tid + (q << 8);           // float4 index 0..1023
            int j   = m >> 2;                   // hidden row 0..255
            int bp4 = m & 3;                    // which 4-b' chunk
            float4 v4 = __ldcg(&src[m]);
            *(float4*)&h_s[(j >> 5) * HS_SL + (bp4 >> 1) * HS_HALF
                           + (j & 31) * 8 + (bp4 & 1) * 4] = v4;
        }
        __syncthreads();
    }

    size_t OUTH = (size_t)T_STEPS * BATCH * HID;
    out[OUTH + (size_t)l * BATCH * HID + b_pw * 256 + hcol]                = h_cur;
    out[OUTH + (size_t)NLAYER * BATCH * HID + (size_t)l * BATCH * HID
        + b_pw * 256 + hcol]                                                = c;
}

// ---------------- launch ----------------------------------------------------
extern "C" void kernel_launch(void* const* d_in, const int* in_sizes, int n_in,
                              void* d_out, int out_size) {
    const float* x    = (const float*)d_in[0];
    const float* h0   = (const float*)d_in[1];
    const float* c0   = (const float*)d_in[2];
    const float* W    = (const float*)d_in[3];
    const float* bias = (const float*)d_in[4];
    float* out = (float*)d_out;

    k_pre<<<NLAYER * (MROWS / 128) * (1024 / 128), 256>>>(x, W, bias);
    k_rec<<<NLAYER * 64, 256>>>(h0, c0, W, out);
}